// round 1
// baseline (speedup 1.0000x reference)
#include <cuda_runtime.h>
#include <cuda_bf16.h>

// CausalSequenceCML: 16 fused steps of depthwise-causal-conv logistic CML.
// B=4, T=4096, C=512, K=4, STEPS=16.
//
// Layout: input/output (B, T, C), channel-contiguous.
// Block = 256 threads = 32 channels x 8 time-strips, 26 cells/thread.
// Time tile = 208 (48-halo + 160 valid). All state in registers; only
// 3 boundary mapped-values per strip per step cross threads via smem.

#define Bdim 4
#define Tdim 4096
#define Cdim 512
#define NSTEPS 16
#define CC 32       // channels per block
#define SS 8        // time strips per block
#define LL 26       // cells per thread
#define TILE (SS * LL)      // 208
#define HALO 48             // 3 * NSTEPS
#define VALID (TILE - HALO) // 160
#define NTILES ((Tdim + VALID - 1) / VALID) // 26

__global__ void __launch_bounds__(256, 2)
cml_kernel(const float* __restrict__ drive,
           const float* __restrict__ r,
           const float* __restrict__ eps,
           const float* __restrict__ beta,
           const float* __restrict__ Kc,
           float* __restrict__ out)
{
    // double-buffered boundary mapped values: [buf][strip][3][channel]
    __shared__ float bm[2][SS][3][CC];

    const int tid = threadIdx.x;
    const int c   = tid & (CC - 1);
    const int s   = tid >> 5;
    const int cg  = blockIdx.y * CC + c;     // global channel
    const int b   = blockIdx.z;
    const int gt0 = (int)blockIdx.x * VALID - HALO;  // tile start (can be -48)
    const int base = b * (Tdim * Cdim);

    // per-channel constants
    const float rr = r[cg];
    const float ee = eps[cg];
    const float bb = beta[cg];
    const float k0 = Kc[cg * 4 + 0];
    const float k1 = Kc[cg * 4 + 1];
    const float k2 = Kc[cg * 4 + 2];
    const float k3 = Kc[cg * 4 + 3];
    const float onemb = 1.0f - bb;
    const float A  = onemb * (1.0f - ee);   // coeff of m (non-conv part)
    const float Bc = onemb * ee;            // coeff of local
    const float w3 = fmaf(Bc, k3, A);       // coeff of m[t]
    const float w2 = Bc * k2;               // m[t-1]
    const float w1 = Bc * k1;               // m[t-2]
    const float w0 = Bc * k0;               // m[t-3]

    // load drive -> g init, D = beta * drive (step-invariant)
    float g[LL], D[LL];
    const int ltbase = s * LL;
#pragma unroll
    for (int i = 0; i < LL; i++) {
        const int gt = gt0 + ltbase + i;
        float d = 0.0f;
        if (gt >= 0 && gt < Tdim)
            d = drive[base + gt * Cdim + cg];
        g[i] = d;
        D[i] = bb * d;
    }

#pragma unroll 1
    for (int step = 0; step < NSTEPS; step++) {
        float* buf = &bm[step & 1][0][0][0];
        // boundary: mapped values of this strip's last 3 cells (for strip s+1)
#pragma unroll
        for (int j = 0; j < 3; j++) {
            const float gi = g[LL - 3 + j];
            const float rg = rr * gi;
            const float mv = fmaf(-rg, gi, rg);      // r*g*(1-g)
            buf[(s * 3 + j) * CC + c] = mv;
        }
        __syncthreads();

        float m3 = 0.0f, m2 = 0.0f, m1 = 0.0f;
        if (s > 0) {
            m3 = buf[((s - 1) * 3 + 0) * CC + c];
            m2 = buf[((s - 1) * 3 + 1) * CC + c];
            m1 = buf[((s - 1) * 3 + 2) * CC + c];
        }
        // main sweep: 6 FMA-class ops per cell
#pragma unroll
        for (int i = 0; i < LL; i++) {
            const float gi = g[i];
            const float rg = rr * gi;
            const float m0 = fmaf(-rg, gi, rg);
            float acc = fmaf(w3, m0, D[i]);
            acc = fmaf(w2, m1, acc);
            acc = fmaf(w1, m2, acc);
            g[i] = fmaf(w0, m3, acc);
            m3 = m2; m2 = m1; m1 = m0;
        }
    }

    // clip + store valid region
#pragma unroll
    for (int i = 0; i < LL; i++) {
        const int lt = ltbase + i;
        const int gt = gt0 + lt;
        if (lt >= HALO && gt < Tdim) {
            float v = fminf(fmaxf(g[i], 1.0e-4f), 1.0f - 1.0e-4f);
            out[base + gt * Cdim + cg] = v;
        }
    }
}

extern "C" void kernel_launch(void* const* d_in, const int* in_sizes, int n_in,
                              void* d_out, int out_size)
{
    const float* drive = (const float*)d_in[0];
    const float* r     = (const float*)d_in[1];
    const float* eps   = (const float*)d_in[2];
    const float* beta  = (const float*)d_in[3];
    const float* Kc    = (const float*)d_in[4];
    float* out = (float*)d_out;

    dim3 grid(NTILES, Cdim / CC, Bdim);   // 26 x 16 x 4
    cml_kernel<<<grid, CC * SS>>>(drive, r, eps, beta, Kc, out);
}